// round 7
// baseline (speedup 1.0000x reference)
#include <cuda_runtime.h>
#include <cuda_bf16.h>
#include <math.h>
#include <stdint.h>

// Problem constants
#define NN   3072
#define HH   8
#define DH   32
#define HID  256
#define DEG  16
#define EE   (NN*DEG)      // 49152
#define EDIM 32
#define FFN  1024

// ---------------------------------------------------------------------------
// Scratch (no allocations allowed -> __device__ globals)
// Packed operand format: uint2 = (bf16x2 hi, bf16x2 lo) covering 2 consecutive
// k-elements. A-layout: [row][k2]. B-layout: [k2][col].
// ---------------------------------------------------------------------------
__device__ float g_Q[NN*HID];
__device__ float g_K[NN*HID];
__device__ float g_V[NN*HID];
__device__ float g_eatt[EE*HH];
__device__ float g_x1[NN*HID];
__device__ float g_part[4][NN*HID];   // split-K partials

__device__ __align__(16) uint2 g_pW4[4][128*256];   // Wq,Wk,Wv,Wo  (B-layout)
__device__ __align__(16) uint2 g_pWf1[128*1024];    // B-layout
__device__ __align__(16) uint2 g_pWf2[512*256];     // B-layout
__device__ __align__(16) uint2 g_pNode[NN*128];     // A-layout
__device__ __align__(16) uint2 g_pAttn[NN*128];     // A-layout
__device__ __align__(16) uint2 g_pX1[NN*128];       // A-layout
__device__ __align__(16) uint2 g_pF[NN*512];        // A-layout

struct Parts4 { float* p[4]; };

// ---------------------------------------------------------------------------
// Helpers
// ---------------------------------------------------------------------------
__device__ __forceinline__ uint32_t b2u(__nv_bfloat162 v) {
    return *reinterpret_cast<uint32_t*>(&v);
}

__device__ __forceinline__ uint2 split_pair(float x, float y) {
    __nv_bfloat162 h = __floats2bfloat162_rn(x, y);
    float rx = x - __bfloat162float(h.x);
    float ry = y - __bfloat162float(h.y);
    __nv_bfloat162 l = __floats2bfloat162_rn(rx, ry);
    return make_uint2(b2u(h), b2u(l));
}

__device__ __forceinline__ uint32_t smem_u32(const void* p) {
    return (uint32_t)__cvta_generic_to_shared(p);
}

#define CP8(dst, src)  asm volatile("cp.async.ca.shared.global [%0], [%1], 8;\n"  :: "r"(dst), "l"(src))
#define CP16(dst, src) asm volatile("cp.async.cg.shared.global [%0], [%1], 16;\n" :: "r"(dst), "l"(src))
#define CP_COMMIT()    asm volatile("cp.async.commit_group;\n")
#define CP_WAIT(n)     asm volatile("cp.async.wait_group %0;\n" :: "n"(n))

__device__ __forceinline__ void mma16(float* c, const uint32_t* a, const uint32_t* b) {
    asm volatile(
        "mma.sync.aligned.m16n8k16.row.col.f32.bf16.bf16.f32 "
        "{%0,%1,%2,%3}, {%4,%5,%6,%7}, {%8,%9}, {%0,%1,%2,%3};\n"
        : "+f"(c[0]), "+f"(c[1]), "+f"(c[2]), "+f"(c[3])
        : "r"(a[0]), "r"(a[1]), "r"(a[2]), "r"(a[3]), "r"(b[0]), "r"(b[1]));
}

// ---------------------------------------------------------------------------
// Prepass: pack all weights (B-layout) + node_states (A-layout).
// ---------------------------------------------------------------------------
struct PackArgs {
    const float* w[6];     // Wq, Wk, Wv, Wo, Wf1, Wf2
    uint2*       pw[6];
    const float* node;
    uint2*       pnode;
};

__global__ void __launch_bounds__(256) pack_all_kernel(PackArgs pa)
{
    int e = blockIdx.x * 1024 + threadIdx.x;
#pragma unroll
    for (int i = 0; i < 4; i++, e += 256) {
        if (e < 131072) {                       // 4 weights, 256x256 (N=256)
            int w  = e >> 15, r = e & 32767;
            int k2 = r >> 8,  col = r & 255;
            const float* W = pa.w[w];
            pa.pw[w][r] = split_pair(W[(2*k2)*256 + col], W[(2*k2+1)*256 + col]);
        } else if (e < 262144) {                // Wf1: N=1024
            int r  = e - 131072;
            int k2 = r >> 10, col = r & 1023;
            pa.pw[4][r] = split_pair(pa.w[4][(2*k2)*1024 + col], pa.w[4][(2*k2+1)*1024 + col]);
        } else if (e < 393216) {                // Wf2: N=256
            int r  = e - 262144;
            int k2 = r >> 8, col = r & 255;
            pa.pw[5][r] = split_pair(pa.w[5][(2*k2)*256 + col], pa.w[5][(2*k2+1)*256 + col]);
        } else {                                // node: A-layout [row][k2]
            int r = e - 393216;
            float2 v = ((const float2*)pa.node)[r];
            pa.pnode[r] = split_pair(v.x, v.y);
        }
    }
}

// ---------------------------------------------------------------------------
// Packed-operand bf16 split GEMM (hh + hl + lh), cp.async double-buffered.
// Block tile 64x64, BK=32 (16 k-pairs), 128 threads (4 warps 2x2).
// ---------------------------------------------------------------------------
#define GBM 64
#define GBN 64
#define KP  16      // k-pairs per stage
#define SSTR 68     // uint2 stride

template<bool RELU, bool BIAS, bool PACKOUT>
__device__ __forceinline__ void gemm_core_p(
    const uint2* __restrict__ Ap, const uint2* __restrict__ Bp,
    const float* __restrict__ bias, float* __restrict__ C, uint2* __restrict__ Cp,
    int Nc, int K2, int kbeg2, int kend2, int bm, int bn, int Kout2)
{
    __shared__ __align__(16) uint2 As[2][KP][SSTR];
    __shared__ __align__(16) uint2 Bs[2][KP][SSTR];

    const int tid  = threadIdx.x;
    const int lane = tid & 31;
    const int warp = tid >> 5;
    const int wm   = (warp & 1) * 32;
    const int wn   = (warp >> 1) * 32;
    const int grp  = lane >> 2;
    const int tig  = lane & 3;

    float acc[2][4][4] = {};

#define ISSUE(bf, k02)                                                          \
    {                                                                           \
        _Pragma("unroll")                                                       \
        for (int it = 0; it < 8; it++) {                                        \
            int idx = tid + it * 128;                                           \
            int row = idx >> 4, k2 = idx & 15;                                  \
            CP8(smem_u32(&As[bf][k2][row]),                                     \
                Ap + (size_t)(bm + row) * K2 + (k02) + k2);                     \
        }                                                                       \
        _Pragma("unroll")                                                       \
        for (int it = 0; it < 4; it++) {                                        \
            int idx = tid + it * 128;                                           \
            int k2 = idx >> 5, cp = idx & 31;                                   \
            CP16(smem_u32(&Bs[bf][k2][2*cp]),                                   \
                 Bp + (size_t)((k02) + k2) * Nc + bn + 2*cp);                   \
        }                                                                       \
        CP_COMMIT();                                                            \
    }

#define COMPUTE(bf)                                                             \
    {                                                                           \
        _Pragma("unroll")                                                       \
        for (int s = 0; s < 2; s++) {                                           \
            const int k2a = s*8 + tig, k2b = s*8 + tig + 4;                     \
            uint32_t ah[2][4], al[2][4], bh[4][2], bl[4][2];                    \
            _Pragma("unroll")                                                   \
            for (int mi = 0; mi < 2; mi++) {                                    \
                int r = wm + mi*16 + grp;                                       \
                uint2 e0 = As[bf][k2a][r], e1 = As[bf][k2a][r+8];               \
                uint2 e2 = As[bf][k2b][r], e3 = As[bf][k2b][r+8];               \
                ah[mi][0]=e0.x; ah[mi][1]=e1.x; ah[mi][2]=e2.x; ah[mi][3]=e3.x; \
                al[mi][0]=e0.y; al[mi][1]=e1.y; al[mi][2]=e2.y; al[mi][3]=e3.y; \
            }                                                                   \
            _Pragma("unroll")                                                   \
            for (int ni = 0; ni < 4; ni++) {                                    \
                int c = wn + ni*8 + grp;                                        \
                uint2 f0 = Bs[bf][k2a][c], f1 = Bs[bf][k2b][c];                 \
                bh[ni][0]=f0.x; bh[ni][1]=f1.x;                                 \
                bl[ni][0]=f0.y; bl[ni][1]=f1.y;                                 \
            }                                                                   \
            _Pragma("unroll")                                                   \
            for (int mi = 0; mi < 2; mi++)                                      \
                _Pragma("unroll")                                               \
                for (int ni = 0; ni < 4; ni++) {                                \
                    mma16(acc[mi][ni], ah[mi], bh[ni]);                         \
                    mma16(acc[mi][ni], ah[mi], bl[ni]);                         \
                    mma16(acc[mi][ni], al[mi], bh[ni]);                         \
                }                                                               \
        }                                                                       \
    }

    ISSUE(0, kbeg2);
    int buf = 0;
#pragma unroll 1
    for (int k02 = kbeg2 + KP; k02 < kend2; k02 += KP) {
        ISSUE(buf ^ 1, k02);
        CP_WAIT(1);
        __syncthreads();
        COMPUTE(buf);
        __syncthreads();
        buf ^= 1;
    }
    CP_WAIT(0);
    __syncthreads();
    COMPUTE(buf);

    // epilogue
#pragma unroll
    for (int mi = 0; mi < 2; mi++) {
#pragma unroll
        for (int ni = 0; ni < 4; ni++) {
            int r = bm + wm + mi*16 + grp;
            int c = bn + wn + ni*8 + tig*2;
            float v0 = acc[mi][ni][0];
            float v1 = acc[mi][ni][1];
            float v2 = acc[mi][ni][2];
            float v3 = acc[mi][ni][3];
            if (BIAS) {
                float b0 = bias[c], b1 = bias[c+1];
                v0 += b0; v1 += b1; v2 += b0; v3 += b1;
            }
            if (RELU) {
                v0 = fmaxf(v0, 0.f); v1 = fmaxf(v1, 0.f);
                v2 = fmaxf(v2, 0.f); v3 = fmaxf(v3, 0.f);
            }
            if (PACKOUT) {
                Cp[(size_t)r * Kout2 + (c >> 1)]       = split_pair(v0, v1);
                Cp[(size_t)(r + 8) * Kout2 + (c >> 1)] = split_pair(v2, v3);
            } else {
                *(float2*)&C[(size_t)r * Nc + c]       = make_float2(v0, v1);
                *(float2*)&C[(size_t)(r + 8) * Nc + c] = make_float2(v2, v3);
            }
        }
    }
#undef ISSUE
#undef COMPUTE
}

// FFN1: bias + relu + packed output
__global__ void __launch_bounds__(128, 4) gemm_ffn1_kernel(
    const uint2* __restrict__ Ap, const uint2* __restrict__ Bp,
    const float* __restrict__ bias, uint2* __restrict__ Cp, int Nc, int K2, int Kout2)
{
    gemm_core_p<true, true, true>(Ap, Bp, bias, nullptr, Cp, Nc, K2, 0, K2,
                                  blockIdx.y * GBM, blockIdx.x * GBN, Kout2);
}

// Split-K partial GEMM (float partials, no bias)
__global__ void __launch_bounds__(128, 4) gemm_split_kernel(
    const uint2* __restrict__ Ap, const uint2* __restrict__ Bp,
    Parts4 parts, int Nc, int K2, int ksplit2)
{
    const int z = blockIdx.z;
    gemm_core_p<false, false, false>(Ap, Bp, nullptr, parts.p[z], nullptr, Nc, K2,
                                     z * ksplit2, (z + 1) * ksplit2,
                                     blockIdx.y * GBM, blockIdx.x * GBN, 0);
}

// Fused QKV: grid.x = 12 -> (which of Q/K/V) x (4 column blocks); float out.
struct QKVArgs {
    const uint2* W;         // g_pW4 base; sel*32768 offset
    const float* b[3];
    float*       O[3];
};

__global__ void __launch_bounds__(128, 4) qkv_gemm_kernel(
    const uint2* __restrict__ Ap, QKVArgs args)
{
    const int sel = blockIdx.x >> 2;
    const int bn  = (blockIdx.x & 3) * GBN;
    gemm_core_p<false, true, false>(Ap, args.W + (size_t)sel * (128*256),
                                    args.b[sel], args.O[sel], nullptr,
                                    HID, 128, 0, 128, blockIdx.y * GBM, bn, 0);
}

// ---------------------------------------------------------------------------
// Edge attention bias: eatt[e,h] = edge_features[e,:] @ We[:,h] + be[h]
// ---------------------------------------------------------------------------
__global__ void edge_kernel(const float* __restrict__ ef,
                            const float* __restrict__ We,
                            const float* __restrict__ be,
                            float* __restrict__ eatt)
{
    __shared__ float sWe[EDIM*HH];
    __shared__ float sbe[HH];
    if (threadIdx.x < EDIM*HH) sWe[threadIdx.x] = We[threadIdx.x];
    if (threadIdx.x < HH)      sbe[threadIdx.x] = be[threadIdx.x];
    __syncthreads();

    int e = blockIdx.x * blockDim.x + threadIdx.x;
    if (e >= EE) return;

    float acc[HH];
#pragma unroll
    for (int h = 0; h < HH; h++) acc[h] = sbe[h];

    const float4* row = (const float4*)(ef + (size_t)e * EDIM);
#pragma unroll
    for (int q = 0; q < EDIM/4; q++) {
        float4 v = row[q];
        const float xs[4] = {v.x, v.y, v.z, v.w};
#pragma unroll
        for (int j = 0; j < 4; j++) {
            float x = xs[j];
            const float* w = &sWe[(q*4 + j) * HH];
#pragma unroll
            for (int h = 0; h < HH; h++) acc[h] = fmaf(x, w[h], acc[h]);
        }
    }
    float4* o = (float4*)(eatt + (size_t)e*HH);
    o[0] = make_float4(acc[0], acc[1], acc[2], acc[3]);
    o[1] = make_float4(acc[4], acc[5], acc[6], acc[7]);
}

// ---------------------------------------------------------------------------
// Sparse attention: one block per node, one warp per head.
// Dedup: keep LAST occurrence of duplicate neighbors (XLA scatter semantics).
// Output written PACKED (A-layout) for the Wo GEMM.
// ---------------------------------------------------------------------------
__global__ void __launch_bounds__(HH*32) attn_kernel(
    const float* __restrict__ Q, const float* __restrict__ K,
    const float* __restrict__ V, const int* __restrict__ nbr,
    const float* __restrict__ eatt, uint2* __restrict__ pout)
{
    const int n = blockIdx.x;
    __shared__ int snb[DEG];
    __shared__ int skeep[DEG];

    const int tid = threadIdx.x;
    if (tid < DEG) snb[tid] = nbr[n*DEG + tid];
    __syncthreads();
    if (tid < DEG) {
        int keep = 1;
        int m = snb[tid];
        for (int j = tid + 1; j < DEG; j++)
            if (snb[j] == m) keep = 0;
        skeep[tid] = keep;
    }
    __syncthreads();

    const int h    = tid >> 5;
    const int lane = tid & 31;
    const unsigned FULL = 0xffffffffu;

    const float q = Q[(size_t)n*HID + h*DH + lane];

    float sc = -1e30f;
#pragma unroll
    for (int j = 0; j < DEG; j++) {
        if (skeep[j]) {
            float v = q * K[(size_t)snb[j]*HID + h*DH + lane];
#pragma unroll
            for (int o = 16; o > 0; o >>= 1)
                v += __shfl_xor_sync(FULL, v, o);
            v = v * 0.17677669529663687f + eatt[(size_t)(n*DEG + j)*HH + h];
            if (lane == j) sc = v;
        }
    }

    float m = sc;
#pragma unroll
    for (int o = 16; o > 0; o >>= 1)
        m = fmaxf(m, __shfl_xor_sync(FULL, m, o));
    float p = (sc > -1e29f) ? __expf(sc - m) : 0.f;
    float s = p;
#pragma unroll
    for (int o = 16; o > 0; o >>= 1)
        s += __shfl_xor_sync(FULL, s, o);
    p /= s;

    float acc = 0.f;
#pragma unroll
    for (int j = 0; j < DEG; j++) {
        if (skeep[j]) {
            float pj = __shfl_sync(FULL, p, j);
            acc = fmaf(pj, V[(size_t)snb[j]*HID + h*DH + lane], acc);
        }
    }
    float an = __shfl_down_sync(FULL, acc, 1);
    if ((lane & 1) == 0)
        pout[(size_t)n*128 + h*16 + (lane >> 1)] = split_pair(acc, an);
}

// ---------------------------------------------------------------------------
// Fused: sum of P split-K partials + bias + residual, then LayerNorm.
// Optionally also writes packed (A-layout) output for the next GEMM.
// ---------------------------------------------------------------------------
template<int P, bool PACK>
__global__ void __launch_bounds__(HID) add_ln_multi(
    Parts4 parts, const float* __restrict__ bias,
    const float* __restrict__ res,
    const float* __restrict__ g, const float* __restrict__ b,
    float* __restrict__ out, uint2* __restrict__ pout)
{
    __shared__ float red[8];
    const int row = blockIdx.x;
    const int tid = threadIdx.x;
    const int lane = tid & 31, w = tid >> 5;
    const unsigned FULL = 0xffffffffu;
    const size_t off = (size_t)row*HID + tid;

    float x = bias[tid] + res[off];
#pragma unroll
    for (int p = 0; p < P; p++) x += parts.p[p][off];

    float v = x;
#pragma unroll
    for (int o = 16; o > 0; o >>= 1) v += __shfl_xor_sync(FULL, v, o);
    if (lane == 0) red[w] = v;
    __syncthreads();
    float t = (tid < 8) ? red[tid] : 0.f;
    if (w == 0) {
#pragma unroll
        for (int o = 4; o > 0; o >>= 1) t += __shfl_xor_sync(FULL, t, o);
        if (lane == 0) red[0] = t;
    }
    __syncthreads();
    float mu = red[0] * (1.f / HID);
    __syncthreads();

    float d = x - mu;
    v = d * d;
#pragma unroll
    for (int o = 16; o > 0; o >>= 1) v += __shfl_xor_sync(FULL, v, o);
    if (lane == 0) red[w] = v;
    __syncthreads();
    t = (tid < 8) ? red[tid] : 0.f;
    if (w == 0) {
#pragma unroll
        for (int o = 4; o > 0; o >>= 1) t += __shfl_xor_sync(FULL, t, o);
        if (lane == 0) red[0] = t;
    }
    __syncthreads();
    float var = red[0] * (1.f / HID);

    float val = d * rsqrtf(var + 1e-5f) * g[tid] + b[tid];
    out[off] = val;
    if (PACK) {
        float nx = __shfl_down_sync(FULL, val, 1);
        if ((tid & 1) == 0)
            pout[(size_t)row*128 + (tid >> 1)] = split_pair(val, nx);
    }
}

// ---------------------------------------------------------------------------
// Launch
// ---------------------------------------------------------------------------
extern "C" void kernel_launch(void* const* d_in, const int* in_sizes, int n_in,
                              void* d_out, int out_size)
{
    const float* node = (const float*)d_in[0];
    const int*   nbr  = (const int*)  d_in[1];
    const float* ef   = (const float*)d_in[2];
    const float* Wq   = (const float*)d_in[3];
    const float* bq   = (const float*)d_in[4];
    const float* Wk   = (const float*)d_in[5];
    const float* bk   = (const float*)d_in[6];
    const float* Wv   = (const float*)d_in[7];
    const float* bv   = (const float*)d_in[8];
    const float* We   = (const float*)d_in[9];
    const float* be   = (const float*)d_in[10];
    const float* Wo   = (const float*)d_in[11];
    const float* bo   = (const float*)d_in[12];
    const float* ln1g = (const float*)d_in[13];
    const float* ln1b = (const float*)d_in[14];
    const float* ln2g = (const float*)d_in[15];
    const float* ln2b = (const float*)d_in[16];
    const float* Wf1  = (const float*)d_in[17];
    const float* bf1  = (const float*)d_in[18];
    const float* Wf2  = (const float*)d_in[19];
    const float* bf2  = (const float*)d_in[20];
    float* out = (float*)d_out;

    static float *Qd = nullptr, *Kd, *Vd, *eattd, *x1d, *partd;
    static uint2 *pW4, *pWf1, *pWf2, *pNode, *pAttn, *pX1, *pF;
    if (!Qd) {
        cudaGetSymbolAddress((void**)&Qd,    g_Q);
        cudaGetSymbolAddress((void**)&Kd,    g_K);
        cudaGetSymbolAddress((void**)&Vd,    g_V);
        cudaGetSymbolAddress((void**)&eattd, g_eatt);
        cudaGetSymbolAddress((void**)&x1d,   g_x1);
        cudaGetSymbolAddress((void**)&partd, g_part);
        cudaGetSymbolAddress((void**)&pW4,   g_pW4);
        cudaGetSymbolAddress((void**)&pWf1,  g_pWf1);
        cudaGetSymbolAddress((void**)&pWf2,  g_pWf2);
        cudaGetSymbolAddress((void**)&pNode, g_pNode);
        cudaGetSymbolAddress((void**)&pAttn, g_pAttn);
        cudaGetSymbolAddress((void**)&pX1,   g_pX1);
        cudaGetSymbolAddress((void**)&pF,    g_pF);
    }
    Parts4 parts;
    for (int i = 0; i < 4; i++) parts.p[i] = partd + (size_t)i * NN * HID;

    // Pack weights + node into (hi,lo) bf16x2 operand format
    PackArgs pa;
    pa.w[0] = Wq; pa.w[1] = Wk; pa.w[2] = Wv; pa.w[3] = Wo; pa.w[4] = Wf1; pa.w[5] = Wf2;
    for (int i = 0; i < 4; i++) pa.pw[i] = pW4 + (size_t)i * (128*256);
    pa.pw[4] = pWf1; pa.pw[5] = pWf2;
    pa.node = node; pa.pnode = pNode;
    pack_all_kernel<<<768, 256>>>(pa);

    // Edge bias (independent of packing)
    edge_kernel<<<(EE + 255)/256, 256>>>(ef, We, be, eattd);

    // Fused QKV projections
    QKVArgs qa;
    qa.W = pW4;
    qa.b[0] = bq; qa.b[1] = bk; qa.b[2] = bv;
    qa.O[0] = Qd; qa.O[1] = Kd; qa.O[2] = Vd;
    qkv_gemm_kernel<<<dim3(12, NN/GBM), 128>>>(pNode, qa);

    // Sparse attention (packed output for Wo)
    attn_kernel<<<NN, HH*32>>>(Qd, Kd, Vd, nbr, eattd, pAttn);

    // Output projection (split-K 2) + fused reduce+bias+residual+LN1
    gemm_split_kernel<<<dim3(HID/GBN, NN/GBM, 2), 128>>>(pAttn, pW4 + 3*(128*256), parts, HID, 128, 64);
    add_ln_multi<2, true><<<NN, HID>>>(parts, bo, node, ln1g, ln1b, x1d, pX1);

    // FFN1 (packed output for FFN2)
    gemm_ffn1_kernel<<<dim3(FFN/GBN, NN/GBM), 128>>>(pX1, pWf1, bf1, pF, FFN, 128, 512);

    // FFN2 (split-K 4) + fused reduce+bias+residual+LN2
    gemm_split_kernel<<<dim3(HID/GBN, NN/GBM, 4), 128>>>(pF, pWf2, parts, HID, 512, 128);
    add_ln_multi<4, false><<<NN, HID>>>(parts, bf2, x1d, ln2g, ln2b, out, nullptr);
}

// round 8
// speedup vs baseline: 1.0143x; 1.0143x over previous
#include <cuda_runtime.h>
#include <cuda_bf16.h>
#include <math.h>
#include <stdint.h>

// Problem constants
#define NN   3072
#define HH   8
#define DH   32
#define HID  256
#define DEG  16
#define EE   (NN*DEG)      // 49152
#define EDIM 32
#define FFN  1024

// ---------------------------------------------------------------------------
// Scratch (no allocations allowed -> __device__ globals)
// Packed operand format: uint2 = (bf16x2 hi, bf16x2 lo) covering 2 consecutive
// k-elements. A-layout: [row][k2]. B-layout: [k2][col].
// ---------------------------------------------------------------------------
__device__ float g_Q[NN*HID];
__device__ float g_K[NN*HID];
__device__ float g_V[NN*HID];
__device__ float g_x1[NN*HID];
__device__ float g_part[4][NN*HID];   // split-K partials

__device__ __align__(16) uint2 g_pW4[4][128*256];   // Wq,Wk,Wv,Wo  (B-layout)
__device__ __align__(16) uint2 g_pWf1[128*1024];    // B-layout
__device__ __align__(16) uint2 g_pWf2[512*256];     // B-layout
__device__ __align__(16) uint2 g_pNode[NN*128];     // A-layout
__device__ __align__(16) uint2 g_pAttn[NN*128];     // A-layout
__device__ __align__(16) uint2 g_pX1[NN*128];       // A-layout
__device__ __align__(16) uint2 g_pF[NN*512];        // A-layout

struct Parts4 { float* p[4]; };

// ---------------------------------------------------------------------------
// Helpers
// ---------------------------------------------------------------------------
__device__ __forceinline__ uint32_t b2u(__nv_bfloat162 v) {
    return *reinterpret_cast<uint32_t*>(&v);
}

__device__ __forceinline__ uint2 split_pair(float x, float y) {
    __nv_bfloat162 h = __floats2bfloat162_rn(x, y);
    float rx = x - __bfloat162float(h.x);
    float ry = y - __bfloat162float(h.y);
    __nv_bfloat162 l = __floats2bfloat162_rn(rx, ry);
    return make_uint2(b2u(h), b2u(l));
}

__device__ __forceinline__ uint32_t smem_u32(const void* p) {
    return (uint32_t)__cvta_generic_to_shared(p);
}

#define CP8(dst, src)  asm volatile("cp.async.ca.shared.global [%0], [%1], 8;\n"  :: "r"(dst), "l"(src))
#define CP16(dst, src) asm volatile("cp.async.cg.shared.global [%0], [%1], 16;\n" :: "r"(dst), "l"(src))
#define CP_COMMIT()    asm volatile("cp.async.commit_group;\n")
#define CP_WAIT(n)     asm volatile("cp.async.wait_group %0;\n" :: "n"(n))

__device__ __forceinline__ void mma16(float* c, const uint32_t* a, const uint32_t* b) {
    asm volatile(
        "mma.sync.aligned.m16n8k16.row.col.f32.bf16.bf16.f32 "
        "{%0,%1,%2,%3}, {%4,%5,%6,%7}, {%8,%9}, {%0,%1,%2,%3};\n"
        : "+f"(c[0]), "+f"(c[1]), "+f"(c[2]), "+f"(c[3])
        : "r"(a[0]), "r"(a[1]), "r"(a[2]), "r"(a[3]), "r"(b[0]), "r"(b[1]));
}

// ---------------------------------------------------------------------------
// Prepass: pack all weights (B-layout) + node_states (A-layout).
// ---------------------------------------------------------------------------
struct PackArgs {
    const float* w[6];     // Wq, Wk, Wv, Wo, Wf1, Wf2
    uint2*       pw[6];
    const float* node;
    uint2*       pnode;
};

__global__ void __launch_bounds__(256) pack_all_kernel(PackArgs pa)
{
    int e = blockIdx.x * 1024 + threadIdx.x;
#pragma unroll
    for (int i = 0; i < 4; i++, e += 256) {
        if (e < 131072) {                       // 4 weights, 256x256 (N=256)
            int w  = e >> 15, r = e & 32767;
            int k2 = r >> 8,  col = r & 255;
            const float* W = pa.w[w];
            pa.pw[w][r] = split_pair(W[(2*k2)*256 + col], W[(2*k2+1)*256 + col]);
        } else if (e < 262144) {                // Wf1: N=1024
            int r  = e - 131072;
            int k2 = r >> 10, col = r & 1023;
            pa.pw[4][r] = split_pair(pa.w[4][(2*k2)*1024 + col], pa.w[4][(2*k2+1)*1024 + col]);
        } else if (e < 393216) {                // Wf2: N=256
            int r  = e - 262144;
            int k2 = r >> 8, col = r & 255;
            pa.pw[5][r] = split_pair(pa.w[5][(2*k2)*256 + col], pa.w[5][(2*k2+1)*256 + col]);
        } else {                                // node: A-layout [row][k2]
            int r = e - 393216;
            float2 v = ((const float2*)pa.node)[r];
            pa.pnode[r] = split_pair(v.x, v.y);
        }
    }
}

// ---------------------------------------------------------------------------
// Packed-operand bf16 split GEMM (hh + hl + lh), cp.async double-buffered.
// Block tile 64x64, BK=32 (16 k-pairs), 128 threads (4 warps 2x2).
// ---------------------------------------------------------------------------
#define GBM 64
#define GBN 64
#define KP  16      // k-pairs per stage
#define SSTR 68     // uint2 stride

template<bool RELU, bool BIAS, bool PACKOUT>
__device__ __forceinline__ void gemm_core_p(
    const uint2* __restrict__ Ap, const uint2* __restrict__ Bp,
    const float* __restrict__ bias, float* __restrict__ C, uint2* __restrict__ Cp,
    int Nc, int K2, int kbeg2, int kend2, int bm, int bn, int Kout2)
{
    __shared__ __align__(16) uint2 As[2][KP][SSTR];
    __shared__ __align__(16) uint2 Bs[2][KP][SSTR];

    const int tid  = threadIdx.x;
    const int lane = tid & 31;
    const int warp = tid >> 5;
    const int wm   = (warp & 1) * 32;
    const int wn   = (warp >> 1) * 32;
    const int grp  = lane >> 2;
    const int tig  = lane & 3;

    float acc[2][4][4] = {};

#define ISSUE(bf, k02)                                                          \
    {                                                                           \
        _Pragma("unroll")                                                       \
        for (int it = 0; it < 8; it++) {                                        \
            int idx = tid + it * 128;                                           \
            int row = idx >> 4, k2 = idx & 15;                                  \
            CP8(smem_u32(&As[bf][k2][row]),                                     \
                Ap + (size_t)(bm + row) * K2 + (k02) + k2);                     \
        }                                                                       \
        _Pragma("unroll")                                                       \
        for (int it = 0; it < 4; it++) {                                        \
            int idx = tid + it * 128;                                           \
            int k2 = idx >> 5, cp = idx & 31;                                   \
            CP16(smem_u32(&Bs[bf][k2][2*cp]),                                   \
                 Bp + (size_t)((k02) + k2) * Nc + bn + 2*cp);                   \
        }                                                                       \
        CP_COMMIT();                                                            \
    }

#define COMPUTE(bf)                                                             \
    {                                                                           \
        _Pragma("unroll")                                                       \
        for (int s = 0; s < 2; s++) {                                           \
            const int k2a = s*8 + tig, k2b = s*8 + tig + 4;                     \
            uint32_t ah[2][4], al[2][4], bh[4][2], bl[4][2];                    \
            _Pragma("unroll")                                                   \
            for (int mi = 0; mi < 2; mi++) {                                    \
                int r = wm + mi*16 + grp;                                       \
                uint2 e0 = As[bf][k2a][r], e1 = As[bf][k2a][r+8];               \
                uint2 e2 = As[bf][k2b][r], e3 = As[bf][k2b][r+8];               \
                ah[mi][0]=e0.x; ah[mi][1]=e1.x; ah[mi][2]=e2.x; ah[mi][3]=e3.x; \
                al[mi][0]=e0.y; al[mi][1]=e1.y; al[mi][2]=e2.y; al[mi][3]=e3.y; \
            }                                                                   \
            _Pragma("unroll")                                                   \
            for (int ni = 0; ni < 4; ni++) {                                    \
                int c = wn + ni*8 + grp;                                        \
                uint2 f0 = Bs[bf][k2a][c], f1 = Bs[bf][k2b][c];                 \
                bh[ni][0]=f0.x; bh[ni][1]=f1.x;                                 \
                bl[ni][0]=f0.y; bl[ni][1]=f1.y;                                 \
            }                                                                   \
            _Pragma("unroll")                                                   \
            for (int mi = 0; mi < 2; mi++)                                      \
                _Pragma("unroll")                                               \
                for (int ni = 0; ni < 4; ni++) {                                \
                    mma16(acc[mi][ni], ah[mi], bh[ni]);                         \
                    mma16(acc[mi][ni], ah[mi], bl[ni]);                         \
                    mma16(acc[mi][ni], al[mi], bh[ni]);                         \
                }                                                               \
        }                                                                       \
    }

    ISSUE(0, kbeg2);
    int buf = 0;
#pragma unroll 1
    for (int k02 = kbeg2 + KP; k02 < kend2; k02 += KP) {
        ISSUE(buf ^ 1, k02);
        CP_WAIT(1);
        __syncthreads();
        COMPUTE(buf);
        __syncthreads();
        buf ^= 1;
    }
    CP_WAIT(0);
    __syncthreads();
    COMPUTE(buf);

    // epilogue
#pragma unroll
    for (int mi = 0; mi < 2; mi++) {
#pragma unroll
        for (int ni = 0; ni < 4; ni++) {
            int r = bm + wm + mi*16 + grp;
            int c = bn + wn + ni*8 + tig*2;
            float v0 = acc[mi][ni][0];
            float v1 = acc[mi][ni][1];
            float v2 = acc[mi][ni][2];
            float v3 = acc[mi][ni][3];
            if (BIAS) {
                float b0 = bias[c], b1 = bias[c+1];
                v0 += b0; v1 += b1; v2 += b0; v3 += b1;
            }
            if (RELU) {
                v0 = fmaxf(v0, 0.f); v1 = fmaxf(v1, 0.f);
                v2 = fmaxf(v2, 0.f); v3 = fmaxf(v3, 0.f);
            }
            if (PACKOUT) {
                Cp[(size_t)r * Kout2 + (c >> 1)]       = split_pair(v0, v1);
                Cp[(size_t)(r + 8) * Kout2 + (c >> 1)] = split_pair(v2, v3);
            } else {
                *(float2*)&C[(size_t)r * Nc + c]       = make_float2(v0, v1);
                *(float2*)&C[(size_t)(r + 8) * Nc + c] = make_float2(v2, v3);
            }
        }
    }
#undef ISSUE
#undef COMPUTE
}

// FFN1: bias + relu + packed output
__global__ void __launch_bounds__(128, 4) gemm_ffn1_kernel(
    const uint2* __restrict__ Ap, const uint2* __restrict__ Bp,
    const float* __restrict__ bias, uint2* __restrict__ Cp, int Nc, int K2, int Kout2)
{
    gemm_core_p<true, true, true>(Ap, Bp, bias, nullptr, Cp, Nc, K2, 0, K2,
                                  blockIdx.y * GBM, blockIdx.x * GBN, Kout2);
}

// Split-K partial GEMM (float partials, no bias)
__global__ void __launch_bounds__(128, 4) gemm_split_kernel(
    const uint2* __restrict__ Ap, const uint2* __restrict__ Bp,
    Parts4 parts, int Nc, int K2, int ksplit2)
{
    const int z = blockIdx.z;
    gemm_core_p<false, false, false>(Ap, Bp, nullptr, parts.p[z], nullptr, Nc, K2,
                                     z * ksplit2, (z + 1) * ksplit2,
                                     blockIdx.y * GBM, blockIdx.x * GBN, 0);
}

// Fused QKV: grid.x = 12 -> (which of Q/K/V) x (4 column blocks); float out.
struct QKVArgs {
    const uint2* W;         // g_pW4 base; sel*32768 offset
    const float* b[3];
    float*       O[3];
};

__global__ void __launch_bounds__(128, 4) qkv_gemm_kernel(
    const uint2* __restrict__ Ap, QKVArgs args)
{
    const int sel = blockIdx.x >> 2;
    const int bn  = (blockIdx.x & 3) * GBN;
    gemm_core_p<false, true, false>(Ap, args.W + (size_t)sel * (128*256),
                                    args.b[sel], args.O[sel], nullptr,
                                    HID, 128, 0, 128, blockIdx.y * GBM, bn, 0);
}

// ---------------------------------------------------------------------------
// Fused sparse attention + edge bias. One block (256 thr) per node.
// Phase A (128 thr, t=(j,h)): full 32-dot Q.K + edge bias ef.We[:,h]+be[h].
// Phase B (128 thr): width-16 shuffle softmax per head.
// Phase C (256 thr, t=(h,d)): output accumulation, coalesced V loads.
// Dedup: keep LAST occurrence of duplicate neighbors (XLA scatter semantics).
// Output written PACKED (A-layout) for the Wo GEMM.
// ---------------------------------------------------------------------------
__global__ void __launch_bounds__(256) attn_fused_kernel(
    const float* __restrict__ Q, const float* __restrict__ K,
    const float* __restrict__ V, const int* __restrict__ nbr,
    const float* __restrict__ ef, const float* __restrict__ We,
    const float* __restrict__ be, uint2* __restrict__ pout)
{
    const int n = blockIdx.x;
    const int t = threadIdx.x;
    const unsigned FULL = 0xffffffffu;

    __shared__ int   snb[DEG];
    __shared__ float keepf[DEG];
    __shared__ float sWe[EDIM*HH];     // 256
    __shared__ float sbe[HH];
    __shared__ float sQ[HID];          // 256
    __shared__ float sef[DEG*EDIM];    // 512
    __shared__ float sc[HH][DEG];
    __shared__ float sp[HH][DEG];

    if (t < DEG) snb[t] = nbr[n*DEG + t];
    sWe[t] = We[t];
    if (t < HH) sbe[t] = be[t];
    sQ[t] = Q[(size_t)n*HID + t];
    {
        const float* efn = ef + (size_t)n * DEG * EDIM;
        sef[t]       = efn[t];
        sef[t + 256] = efn[t + 256];
    }
    __syncthreads();
    if (t < DEG) {
        int keep = 1, m = snb[t];
        for (int j2 = t + 1; j2 < DEG; j2++)
            if (snb[j2] == m) keep = 0;
        keepf[t] = (float)keep;
    }
    __syncthreads();

    // Phase A: scores + edge bias
    if (t < 128) {
        const int j = t >> 3, h = t & 7;
        const float* kr = K + (size_t)snb[j]*HID + h*DH;
        const float* qr = sQ + h*DH;
        float dot = 0.f;
#pragma unroll
        for (int i = 0; i < 8; i++) {
            float4 kv = *(const float4*)(kr + i*4);
            float4 qv = *(const float4*)(qr + i*4);
            dot += kv.x*qv.x + kv.y*qv.y + kv.z*qv.z + kv.w*qv.w;
        }
        float eb = sbe[h];
        const float* er = sef + j*EDIM;
#pragma unroll
        for (int k = 0; k < EDIM; k++) eb = fmaf(er[k], sWe[k*HH + h], eb);
        float s = dot * 0.17677669529663687f + eb;
        sc[h][j] = (keepf[j] > 0.5f) ? s : -1e30f;
    }
    __syncthreads();

    // Phase B: softmax over 16 neighbors per head (width-16 shuffles)
    if (t < 128) {
        const int h = t >> 4, j = t & 15;
        float v = sc[h][j];
        float m = v;
#pragma unroll
        for (int o = 8; o > 0; o >>= 1)
            m = fmaxf(m, __shfl_xor_sync(FULL, m, o, 16));
        float p = (v > -1e29f) ? __expf(v - m) : 0.f;
        float ssum = p;
#pragma unroll
        for (int o = 8; o > 0; o >>= 1)
            ssum += __shfl_xor_sync(FULL, ssum, o, 16);
        sp[h][j] = p / ssum;
    }
    __syncthreads();

    // Phase C: output, coalesced V loads; pack pairs for Wo GEMM.
    {
        const int h = t >> 5, d = t & 31;
        float acc = 0.f;
#pragma unroll
        for (int j = 0; j < DEG; j++) {
            float pj = sp[h][j];
            acc = fmaf(pj, V[(size_t)snb[j]*HID + h*DH + d], acc);
        }
        float an = __shfl_down_sync(FULL, acc, 1);
        if ((d & 1) == 0)
            pout[(size_t)n*128 + h*16 + (d >> 1)] = split_pair(acc, an);
    }
}

// ---------------------------------------------------------------------------
// Fused: sum of P split-K partials + bias + residual, then LayerNorm.
// Optionally also writes packed (A-layout) output for the next GEMM.
// ---------------------------------------------------------------------------
template<int P, bool PACK>
__global__ void __launch_bounds__(HID) add_ln_multi(
    Parts4 parts, const float* __restrict__ bias,
    const float* __restrict__ res,
    const float* __restrict__ g, const float* __restrict__ b,
    float* __restrict__ out, uint2* __restrict__ pout)
{
    __shared__ float red[8];
    const int row = blockIdx.x;
    const int tid = threadIdx.x;
    const int lane = tid & 31, w = tid >> 5;
    const unsigned FULL = 0xffffffffu;
    const size_t off = (size_t)row*HID + tid;

    float x = bias[tid] + res[off];
#pragma unroll
    for (int p = 0; p < P; p++) x += parts.p[p][off];

    float v = x;
#pragma unroll
    for (int o = 16; o > 0; o >>= 1) v += __shfl_xor_sync(FULL, v, o);
    if (lane == 0) red[w] = v;
    __syncthreads();
    float t = (tid < 8) ? red[tid] : 0.f;
    if (w == 0) {
#pragma unroll
        for (int o = 4; o > 0; o >>= 1) t += __shfl_xor_sync(FULL, t, o);
        if (lane == 0) red[0] = t;
    }
    __syncthreads();
    float mu = red[0] * (1.f / HID);
    __syncthreads();

    float d = x - mu;
    v = d * d;
#pragma unroll
    for (int o = 16; o > 0; o >>= 1) v += __shfl_xor_sync(FULL, v, o);
    if (lane == 0) red[w] = v;
    __syncthreads();
    t = (tid < 8) ? red[tid] : 0.f;
    if (w == 0) {
#pragma unroll
        for (int o = 4; o > 0; o >>= 1) t += __shfl_xor_sync(FULL, t, o);
        if (lane == 0) red[0] = t;
    }
    __syncthreads();
    float var = red[0] * (1.f / HID);

    float val = d * rsqrtf(var + 1e-5f) * g[tid] + b[tid];
    out[off] = val;
    if (PACK) {
        float nx = __shfl_down_sync(FULL, val, 1);
        if ((tid & 1) == 0)
            pout[(size_t)row*128 + (tid >> 1)] = split_pair(val, nx);
    }
}

// ---------------------------------------------------------------------------
// Launch
// ---------------------------------------------------------------------------
extern "C" void kernel_launch(void* const* d_in, const int* in_sizes, int n_in,
                              void* d_out, int out_size)
{
    const float* node = (const float*)d_in[0];
    const int*   nbr  = (const int*)  d_in[1];
    const float* ef   = (const float*)d_in[2];
    const float* Wq   = (const float*)d_in[3];
    const float* bq   = (const float*)d_in[4];
    const float* Wk   = (const float*)d_in[5];
    const float* bk   = (const float*)d_in[6];
    const float* Wv   = (const float*)d_in[7];
    const float* bv   = (const float*)d_in[8];
    const float* We   = (const float*)d_in[9];
    const float* be   = (const float*)d_in[10];
    const float* Wo   = (const float*)d_in[11];
    const float* bo   = (const float*)d_in[12];
    const float* ln1g = (const float*)d_in[13];
    const float* ln1b = (const float*)d_in[14];
    const float* ln2g = (const float*)d_in[15];
    const float* ln2b = (const float*)d_in[16];
    const float* Wf1  = (const float*)d_in[17];
    const float* bf1  = (const float*)d_in[18];
    const float* Wf2  = (const float*)d_in[19];
    const float* bf2  = (const float*)d_in[20];
    float* out = (float*)d_out;

    static float *Qd = nullptr, *Kd, *Vd, *x1d, *partd;
    static uint2 *pW4, *pWf1, *pWf2, *pNode, *pAttn, *pX1, *pF;
    if (!Qd) {
        cudaGetSymbolAddress((void**)&Qd,    g_Q);
        cudaGetSymbolAddress((void**)&Kd,    g_K);
        cudaGetSymbolAddress((void**)&Vd,    g_V);
        cudaGetSymbolAddress((void**)&x1d,   g_x1);
        cudaGetSymbolAddress((void**)&partd, g_part);
        cudaGetSymbolAddress((void**)&pW4,   g_pW4);
        cudaGetSymbolAddress((void**)&pWf1,  g_pWf1);
        cudaGetSymbolAddress((void**)&pWf2,  g_pWf2);
        cudaGetSymbolAddress((void**)&pNode, g_pNode);
        cudaGetSymbolAddress((void**)&pAttn, g_pAttn);
        cudaGetSymbolAddress((void**)&pX1,   g_pX1);
        cudaGetSymbolAddress((void**)&pF,    g_pF);
    }
    Parts4 parts;
    for (int i = 0; i < 4; i++) parts.p[i] = partd + (size_t)i * NN * HID;

    // Pack weights + node into (hi,lo) bf16x2 operand format
    PackArgs pa;
    pa.w[0] = Wq; pa.w[1] = Wk; pa.w[2] = Wv; pa.w[3] = Wo; pa.w[4] = Wf1; pa.w[5] = Wf2;
    for (int i = 0; i < 4; i++) pa.pw[i] = pW4 + (size_t)i * (128*256);
    pa.pw[4] = pWf1; pa.pw[5] = pWf2;
    pa.node = node; pa.pnode = pNode;
    pack_all_kernel<<<768, 256>>>(pa);

    // Fused QKV projections
    QKVArgs qa;
    qa.W = pW4;
    qa.b[0] = bq; qa.b[1] = bk; qa.b[2] = bv;
    qa.O[0] = Qd; qa.O[1] = Kd; qa.O[2] = Vd;
    qkv_gemm_kernel<<<dim3(12, NN/GBM), 128>>>(pNode, qa);

    // Fused sparse attention + edge bias (packed output for Wo)
    attn_fused_kernel<<<NN, 256>>>(Qd, Kd, Vd, nbr, ef, We, be, pAttn);

    // Output projection (split-K 2) + fused reduce+bias+residual+LN1
    gemm_split_kernel<<<dim3(HID/GBN, NN/GBM, 2), 128>>>(pAttn, pW4 + 3*(128*256), parts, HID, 128, 64);
    add_ln_multi<2, true><<<NN, HID>>>(parts, bo, node, ln1g, ln1b, x1d, pX1);

    // FFN1 (packed output for FFN2)
    gemm_ffn1_kernel<<<dim3(FFN/GBN, NN/GBM), 128>>>(pX1, pWf1, bf1, pF, FFN, 128, 512);

    // FFN2 (split-K 4) + fused reduce+bias+residual+LN2
    gemm_split_kernel<<<dim3(HID/GBN, NN/GBM, 4), 128>>>(pF, pWf2, parts, HID, 512, 128);
    add_ln_multi<4, false><<<NN, HID>>>(parts, bf2, x1d, ln2g, ln2b, out, nullptr);
}

// round 9
// speedup vs baseline: 1.1094x; 1.0938x over previous
#include <cuda_runtime.h>
#include <cuda_bf16.h>
#include <math.h>
#include <stdint.h>

// Problem constants
#define NN   3072
#define HH   8
#define DH   32
#define HID  256
#define DEG  16
#define EE   (NN*DEG)      // 49152
#define EDIM 32
#define FFN  1024

// ---------------------------------------------------------------------------
// Scratch (no allocations allowed -> __device__ globals)
// Packed operand format: uint2 = (bf16x2 hi, bf16x2 lo) covering 2 consecutive
// k-elements. A-layout: [row][k2]. B-layout: [k2][col].
// ---------------------------------------------------------------------------
__device__ float g_Q[NN*HID];
__device__ float g_K[NN*HID];
__device__ float g_V[NN*HID];
__device__ float g_x1[NN*HID];
__device__ float g_part[4][NN*HID];   // split-K partials

__device__ __align__(16) uint2 g_pW4[4][128*256];   // Wq,Wk,Wv,Wo  (B-layout)
__device__ __align__(16) uint2 g_pWf1[128*1024];    // B-layout
__device__ __align__(16) uint2 g_pWf2[512*256];     // B-layout
__device__ __align__(16) uint2 g_pNode[NN*128];     // A-layout
__device__ __align__(16) uint2 g_pAttn[NN*128];     // A-layout
__device__ __align__(16) uint2 g_pX1[NN*128];       // A-layout
__device__ __align__(16) uint2 g_pF[NN*512];        // A-layout

struct Parts4 { float* p[4]; };

// ---------------------------------------------------------------------------
// Helpers
// ---------------------------------------------------------------------------
__device__ __forceinline__ uint32_t b2u(__nv_bfloat162 v) {
    return *reinterpret_cast<uint32_t*>(&v);
}

__device__ __forceinline__ uint2 split_pair(float x, float y) {
    __nv_bfloat162 h = __floats2bfloat162_rn(x, y);
    float rx = x - __bfloat162float(h.x);
    float ry = y - __bfloat162float(h.y);
    __nv_bfloat162 l = __floats2bfloat162_rn(rx, ry);
    return make_uint2(b2u(h), b2u(l));
}

__device__ __forceinline__ uint32_t smem_u32(const void* p) {
    return (uint32_t)__cvta_generic_to_shared(p);
}

#define CP8(dst, src)  asm volatile("cp.async.ca.shared.global [%0], [%1], 8;\n"  :: "r"(smem_u32(dst)), "l"(src))
#define CP16(dst, src) asm volatile("cp.async.cg.shared.global [%0], [%1], 16;\n" :: "r"(smem_u32(dst)), "l"(src))
#define CP_COMMIT()    asm volatile("cp.async.commit_group;\n")
#define CP_WAIT(n)     asm volatile("cp.async.wait_group %0;\n" :: "n"(n))

__device__ __forceinline__ void mma16(float* c, const uint32_t* a, const uint32_t* b) {
    asm volatile(
        "mma.sync.aligned.m16n8k16.row.col.f32.bf16.bf16.f32 "
        "{%0,%1,%2,%3}, {%4,%5,%6,%7}, {%8,%9}, {%0,%1,%2,%3};\n"
        : "+f"(c[0]), "+f"(c[1]), "+f"(c[2]), "+f"(c[3])
        : "r"(a[0]), "r"(a[1]), "r"(a[2]), "r"(a[3]), "r"(b[0]), "r"(b[1]));
}

// ---------------------------------------------------------------------------
// Prepass: pack all weights (B-layout) + node_states (A-layout).
// ---------------------------------------------------------------------------
struct PackArgs {
    const float* w[6];     // Wq, Wk, Wv, Wo, Wf1, Wf2
    uint2*       pw[6];
    const float* node;
    uint2*       pnode;
};

__global__ void __launch_bounds__(256) pack_all_kernel(PackArgs pa)
{
    int e = blockIdx.x * 1024 + threadIdx.x;
#pragma unroll
    for (int i = 0; i < 4; i++, e += 256) {
        if (e < 131072) {                       // 4 weights, 256x256 (N=256)
            int w  = e >> 15, r = e & 32767;
            int k2 = r >> 8,  col = r & 255;
            const float* W = pa.w[w];
            pa.pw[w][r] = split_pair(W[(2*k2)*256 + col], W[(2*k2+1)*256 + col]);
        } else if (e < 262144) {                // Wf1: N=1024
            int r  = e - 131072;
            int k2 = r >> 10, col = r & 1023;
            pa.pw[4][r] = split_pair(pa.w[4][(2*k2)*1024 + col], pa.w[4][(2*k2+1)*1024 + col]);
        } else if (e < 393216) {                // Wf2: N=256
            int r  = e - 262144;
            int k2 = r >> 8, col = r & 255;
            pa.pw[5][r] = split_pair(pa.w[5][(2*k2)*256 + col], pa.w[5][(2*k2+1)*256 + col]);
        } else {                                // node: A-layout [row][k2]
            int r = e - 393216;
            float2 v = ((const float2*)pa.node)[r];
            pa.pnode[r] = split_pair(v.x, v.y);
        }
    }
}

// ---------------------------------------------------------------------------
// Packed-operand bf16 split GEMM (hh + hl + lh).
// 3-stage cp.async ring, ONE __syncthreads per k-iteration.
// Block tile 64x64, BK=32 (16 k-pairs), 128 threads (4 warps 2x2).
// Dynamic smem: 3 * (A stage + B stage) = 3 * 2 * KP * SSTR * 8 bytes.
// ---------------------------------------------------------------------------
#define GBM 64
#define GBN 64
#define KP  16      // k-pairs per stage
#define SSTR 68     // uint2 stride
#define GEMM_SMEM (3 * 2 * KP * SSTR * 8)

template<bool RELU, bool BIAS, bool PACKOUT>
__device__ __forceinline__ void gemm_core_p(
    const uint2* __restrict__ Ap, const uint2* __restrict__ Bp,
    const float* __restrict__ bias, float* __restrict__ C, uint2* __restrict__ Cp,
    int Nc, int K2, int kbeg2, int kend2, int bm, int bn, int Kout2)
{
    extern __shared__ __align__(16) uint2 sm[];
#define AS(bf) (sm + (bf) * (2*KP*SSTR))
#define BS(bf) (sm + (bf) * (2*KP*SSTR) + KP*SSTR)

    const int tid  = threadIdx.x;
    const int lane = tid & 31;
    const int warp = tid >> 5;
    const int wm   = (warp & 1) * 32;
    const int wn   = (warp >> 1) * 32;
    const int grp  = lane >> 2;
    const int tig  = lane & 3;

    float acc[2][4][4] = {};

#define ISSUE(bf, k02)                                                          \
    {                                                                           \
        _Pragma("unroll")                                                       \
        for (int it = 0; it < 8; it++) {                                        \
            int idx = tid + it * 128;                                           \
            int row = idx >> 4, k2 = idx & 15;                                  \
            CP8(&AS(bf)[k2*SSTR + row],                                         \
                Ap + (size_t)(bm + row) * K2 + (k02) + k2);                     \
        }                                                                       \
        _Pragma("unroll")                                                       \
        for (int it = 0; it < 4; it++) {                                        \
            int idx = tid + it * 128;                                           \
            int k2 = idx >> 5, cp = idx & 31;                                   \
            CP16(&BS(bf)[k2*SSTR + 2*cp],                                       \
                 Bp + (size_t)((k02) + k2) * Nc + bn + 2*cp);                   \
        }                                                                       \
        CP_COMMIT();                                                            \
    }

#define COMPUTE(bf)                                                             \
    {                                                                           \
        _Pragma("unroll")                                                       \
        for (int s = 0; s < 2; s++) {                                           \
            const int k2a = s*8 + tig, k2b = s*8 + tig + 4;                     \
            uint32_t ah[2][4], al[2][4], bh[4][2], bl[4][2];                    \
            _Pragma("unroll")                                                   \
            for (int mi = 0; mi < 2; mi++) {                                    \
                int r = wm + mi*16 + grp;                                       \
                uint2 e0 = AS(bf)[k2a*SSTR + r], e1 = AS(bf)[k2a*SSTR + r+8];   \
                uint2 e2 = AS(bf)[k2b*SSTR + r], e3 = AS(bf)[k2b*SSTR + r+8];   \
                ah[mi][0]=e0.x; ah[mi][1]=e1.x; ah[mi][2]=e2.x; ah[mi][3]=e3.x; \
                al[mi][0]=e0.y; al[mi][1]=e1.y; al[mi][2]=e2.y; al[mi][3]=e3.y; \
            }                                                                   \
            _Pragma("unroll")                                                   \
            for (int ni = 0; ni < 4; ni++) {                                    \
                int c = wn + ni*8 + grp;                                        \
                uint2 f0 = BS(bf)[k2a*SSTR + c], f1 = BS(bf)[k2b*SSTR + c];     \
                bh[ni][0]=f0.x; bh[ni][1]=f1.x;                                 \
                bl[ni][0]=f0.y; bl[ni][1]=f1.y;                                 \
            }                                                                   \
            _Pragma("unroll")                                                   \
            for (int mi = 0; mi < 2; mi++)                                      \
                _Pragma("unroll")                                               \
                for (int ni = 0; ni < 4; ni++) {                                \
                    mma16(acc[mi][ni], ah[mi], bh[ni]);                         \
                    mma16(acc[mi][ni], ah[mi], bl[ni]);                         \
                    mma16(acc[mi][ni], al[mi], bh[ni]);                         \
                }                                                               \
        }                                                                       \
    }

    const int nIter = (kend2 - kbeg2) / KP;
    ISSUE(0, kbeg2);
    if (nIter > 1) ISSUE(1, kbeg2 + KP);

    int bc = 0, b2 = 2;
#pragma unroll 1
    for (int i = 0; i < nIter - 1; i++) {
        CP_WAIT(1);             // stage i resident (2 groups max in flight)
        __syncthreads();        // all threads' copies for stage i visible
        COMPUTE(bc);
        if (i + 2 < nIter)      // refill stage (i+2)%3 == buffer just freed
            ISSUE(b2, kbeg2 + (i + 2) * KP);
        bc = (bc == 2) ? 0 : bc + 1;
        b2 = (b2 == 2) ? 0 : b2 + 1;
    }
    CP_WAIT(0);
    __syncthreads();
    COMPUTE(bc);

    // epilogue
#pragma unroll
    for (int mi = 0; mi < 2; mi++) {
#pragma unroll
        for (int ni = 0; ni < 4; ni++) {
            int r = bm + wm + mi*16 + grp;
            int c = bn + wn + ni*8 + tig*2;
            float v0 = acc[mi][ni][0];
            float v1 = acc[mi][ni][1];
            float v2 = acc[mi][ni][2];
            float v3 = acc[mi][ni][3];
            if (BIAS) {
                float b0 = bias[c], b1 = bias[c+1];
                v0 += b0; v1 += b1; v2 += b0; v3 += b1;
            }
            if (RELU) {
                v0 = fmaxf(v0, 0.f); v1 = fmaxf(v1, 0.f);
                v2 = fmaxf(v2, 0.f); v3 = fmaxf(v3, 0.f);
            }
            if (PACKOUT) {
                Cp[(size_t)r * Kout2 + (c >> 1)]       = split_pair(v0, v1);
                Cp[(size_t)(r + 8) * Kout2 + (c >> 1)] = split_pair(v2, v3);
            } else {
                *(float2*)&C[(size_t)r * Nc + c]       = make_float2(v0, v1);
                *(float2*)&C[(size_t)(r + 8) * Nc + c] = make_float2(v2, v3);
            }
        }
    }
#undef ISSUE
#undef COMPUTE
#undef AS
#undef BS
}

// FFN1: bias + relu + packed output
__global__ void __launch_bounds__(128, 4) gemm_ffn1_kernel(
    const uint2* __restrict__ Ap, const uint2* __restrict__ Bp,
    const float* __restrict__ bias, uint2* __restrict__ Cp, int Nc, int K2, int Kout2)
{
    gemm_core_p<true, true, true>(Ap, Bp, bias, nullptr, Cp, Nc, K2, 0, K2,
                                  blockIdx.y * GBM, blockIdx.x * GBN, Kout2);
}

// Split-K partial GEMM (float partials, no bias)
__global__ void __launch_bounds__(128, 4) gemm_split_kernel(
    const uint2* __restrict__ Ap, const uint2* __restrict__ Bp,
    Parts4 parts, int Nc, int K2, int ksplit2)
{
    const int z = blockIdx.z;
    gemm_core_p<false, false, false>(Ap, Bp, nullptr, parts.p[z], nullptr, Nc, K2,
                                     z * ksplit2, (z + 1) * ksplit2,
                                     blockIdx.y * GBM, blockIdx.x * GBN, 0);
}

// Fused QKV: grid.x = 12 -> (which of Q/K/V) x (4 column blocks); float out.
struct QKVArgs {
    const uint2* W;         // g_pW4 base; sel*32768 offset
    const float* b[3];
    float*       O[3];
};

__global__ void __launch_bounds__(128, 4) qkv_gemm_kernel(
    const uint2* __restrict__ Ap, QKVArgs args)
{
    const int sel = blockIdx.x >> 2;
    const int bn  = (blockIdx.x & 3) * GBN;
    gemm_core_p<false, true, false>(Ap, args.W + (size_t)sel * (128*256),
                                    args.b[sel], args.O[sel], nullptr,
                                    HID, 128, 0, 128, blockIdx.y * GBM, bn, 0);
}

// ---------------------------------------------------------------------------
// Fused sparse attention + edge bias. One block (256 thr) per node.
// Phase A (256 thr, t=(j,h,half)): 16-elem half-dot Q.K + half edge bias,
//          combined across the adjacent lane with one shfl.
// Phase B (128 thr): width-16 shuffle softmax per head.
// Phase C (256 thr, t=(h,d)): output accumulation, coalesced V loads.
// Dedup: keep LAST occurrence of duplicate neighbors (XLA scatter semantics).
// Output written PACKED (A-layout) for the Wo GEMM.
// ---------------------------------------------------------------------------
__global__ void __launch_bounds__(256) attn_fused_kernel(
    const float* __restrict__ Q, const float* __restrict__ K,
    const float* __restrict__ V, const int* __restrict__ nbr,
    const float* __restrict__ ef, const float* __restrict__ We,
    const float* __restrict__ be, uint2* __restrict__ pout)
{
    const int n = blockIdx.x;
    const int t = threadIdx.x;
    const unsigned FULL = 0xffffffffu;

    __shared__ int   snb[DEG];
    __shared__ float keepf[DEG];
    __shared__ float sWe[EDIM*HH];     // 256
    __shared__ float sbe[HH];
    __shared__ float sQ[HID];          // 256
    __shared__ float sef[DEG*EDIM];    // 512
    __shared__ float sc[HH][DEG];
    __shared__ float sp[HH][DEG];

    if (t < DEG) snb[t] = nbr[n*DEG + t];
    sWe[t] = We[t];
    if (t < HH) sbe[t] = be[t];
    sQ[t] = Q[(size_t)n*HID + t];
    {
        const float* efn = ef + (size_t)n * DEG * EDIM;
        sef[t]       = efn[t];
        sef[t + 256] = efn[t + 256];
    }
    __syncthreads();
    if (t < DEG) {
        int keep = 1, m = snb[t];
        for (int j2 = t + 1; j2 < DEG; j2++)
            if (snb[j2] == m) keep = 0;
        keepf[t] = (float)keep;
    }
    __syncthreads();

    // Phase A: scores + edge bias, all 256 threads (two half-dots per (j,h))
    {
        const int j = t >> 4, h = (t >> 1) & 7, half = t & 1;
        const float* kr = K + (size_t)snb[j]*HID + h*DH + half*16;
        const float* qr = sQ + h*DH + half*16;
        float dot = 0.f;
#pragma unroll
        for (int i = 0; i < 4; i++) {
            float4 kv = *(const float4*)(kr + i*4);
            float4 qv = *(const float4*)(qr + i*4);
            dot += kv.x*qv.x + kv.y*qv.y + kv.z*qv.z + kv.w*qv.w;
        }
        float eb = half ? 0.f : sbe[h];
        const float* er = sef + j*EDIM + half*16;
        const float* wcol = sWe + half*16*HH + h;
#pragma unroll
        for (int k = 0; k < 16; k++) eb = fmaf(er[k], wcol[k*HH], eb);
        float v = dot * 0.17677669529663687f + eb;
        v += __shfl_xor_sync(FULL, v, 1);
        if (!half) sc[h][j] = (keepf[j] > 0.5f) ? v : -1e30f;
    }
    __syncthreads();

    // Phase B: softmax over 16 neighbors per head (width-16 shuffles)
    if (t < 128) {
        const int h = t >> 4, j = t & 15;
        float v = sc[h][j];
        float m = v;
#pragma unroll
        for (int o = 8; o > 0; o >>= 1)
            m = fmaxf(m, __shfl_xor_sync(FULL, m, o, 16));
        float p = (v > -1e29f) ? __expf(v - m) : 0.f;
        float ssum = p;
#pragma unroll
        for (int o = 8; o > 0; o >>= 1)
            ssum += __shfl_xor_sync(FULL, ssum, o, 16);
        sp[h][j] = p / ssum;
    }
    __syncthreads();

    // Phase C: output, coalesced V loads; pack pairs for Wo GEMM.
    {
        const int h = t >> 5, d = t & 31;
        float acc = 0.f;
#pragma unroll
        for (int j = 0; j < DEG; j++) {
            float pj = sp[h][j];
            acc = fmaf(pj, V[(size_t)snb[j]*HID + h*DH + d], acc);
        }
        float an = __shfl_down_sync(FULL, acc, 1);
        if ((d & 1) == 0)
            pout[(size_t)n*128 + h*16 + (d >> 1)] = split_pair(acc, an);
    }
}

// ---------------------------------------------------------------------------
// Fused: sum of P split-K partials + bias + residual, then LayerNorm.
// Optionally also writes packed (A-layout) output for the next GEMM.
// ---------------------------------------------------------------------------
template<int P, bool PACK>
__global__ void __launch_bounds__(HID) add_ln_multi(
    Parts4 parts, const float* __restrict__ bias,
    const float* __restrict__ res,
    const float* __restrict__ g, const float* __restrict__ b,
    float* __restrict__ out, uint2* __restrict__ pout)
{
    __shared__ float red[8];
    const int row = blockIdx.x;
    const int tid = threadIdx.x;
    const int lane = tid & 31, w = tid >> 5;
    const unsigned FULL = 0xffffffffu;
    const size_t off = (size_t)row*HID + tid;

    float x = bias[tid] + res[off];
#pragma unroll
    for (int p = 0; p < P; p++) x += parts.p[p][off];

    float v = x;
#pragma unroll
    for (int o = 16; o > 0; o >>= 1) v += __shfl_xor_sync(FULL, v, o);
    if (lane == 0) red[w] = v;
    __syncthreads();
    float t = (tid < 8) ? red[tid] : 0.f;
    if (w == 0) {
#pragma unroll
        for (int o = 4; o > 0; o >>= 1) t += __shfl_xor_sync(FULL, t, o);
        if (lane == 0) red[0] = t;
    }
    __syncthreads();
    float mu = red[0] * (1.f / HID);
    __syncthreads();

    float d = x - mu;
    v = d * d;
#pragma unroll
    for (int o = 16; o > 0; o >>= 1) v += __shfl_xor_sync(FULL, v, o);
    if (lane == 0) red[w] = v;
    __syncthreads();
    t = (tid < 8) ? red[tid] : 0.f;
    if (w == 0) {
#pragma unroll
        for (int o = 4; o > 0; o >>= 1) t += __shfl_xor_sync(FULL, t, o);
        if (lane == 0) red[0] = t;
    }
    __syncthreads();
    float var = red[0] * (1.f / HID);

    float val = d * rsqrtf(var + 1e-5f) * g[tid] + b[tid];
    out[off] = val;
    if (PACK) {
        float nx = __shfl_down_sync(FULL, val, 1);
        if ((tid & 1) == 0)
            pout[(size_t)row*128 + (tid >> 1)] = split_pair(val, nx);
    }
}

// ---------------------------------------------------------------------------
// Launch
// ---------------------------------------------------------------------------
extern "C" void kernel_launch(void* const* d_in, const int* in_sizes, int n_in,
                              void* d_out, int out_size)
{
    const float* node = (const float*)d_in[0];
    const int*   nbr  = (const int*)  d_in[1];
    const float* ef   = (const float*)d_in[2];
    const float* Wq   = (const float*)d_in[3];
    const float* bq   = (const float*)d_in[4];
    const float* Wk   = (const float*)d_in[5];
    const float* bk   = (const float*)d_in[6];
    const float* Wv   = (const float*)d_in[7];
    const float* bv   = (const float*)d_in[8];
    const float* We   = (const float*)d_in[9];
    const float* be   = (const float*)d_in[10];
    const float* Wo   = (const float*)d_in[11];
    const float* bo   = (const float*)d_in[12];
    const float* ln1g = (const float*)d_in[13];
    const float* ln1b = (const float*)d_in[14];
    const float* ln2g = (const float*)d_in[15];
    const float* ln2b = (const float*)d_in[16];
    const float* Wf1  = (const float*)d_in[17];
    const float* bf1  = (const float*)d_in[18];
    const float* Wf2  = (const float*)d_in[19];
    const float* bf2  = (const float*)d_in[20];
    float* out = (float*)d_out;

    static float *Qd = nullptr, *Kd, *Vd, *x1d, *partd;
    static uint2 *pW4, *pWf1, *pWf2, *pNode, *pAttn, *pX1, *pF;
    if (!Qd) {
        cudaGetSymbolAddress((void**)&Qd,    g_Q);
        cudaGetSymbolAddress((void**)&Kd,    g_K);
        cudaGetSymbolAddress((void**)&Vd,    g_V);
        cudaGetSymbolAddress((void**)&x1d,   g_x1);
        cudaGetSymbolAddress((void**)&partd, g_part);
        cudaGetSymbolAddress((void**)&pW4,   g_pW4);
        cudaGetSymbolAddress((void**)&pWf1,  g_pWf1);
        cudaGetSymbolAddress((void**)&pWf2,  g_pWf2);
        cudaGetSymbolAddress((void**)&pNode, g_pNode);
        cudaGetSymbolAddress((void**)&pAttn, g_pAttn);
        cudaGetSymbolAddress((void**)&pX1,   g_pX1);
        cudaGetSymbolAddress((void**)&pF,    g_pF);
        // 3-stage ring needs >48KB smem -> opt in once (outside capture).
        cudaFuncSetAttribute(qkv_gemm_kernel,
            cudaFuncAttributeMaxDynamicSharedMemorySize, GEMM_SMEM);
        cudaFuncSetAttribute(gemm_ffn1_kernel,
            cudaFuncAttributeMaxDynamicSharedMemorySize, GEMM_SMEM);
        cudaFuncSetAttribute(gemm_split_kernel,
            cudaFuncAttributeMaxDynamicSharedMemorySize, GEMM_SMEM);
    }
    Parts4 parts;
    for (int i = 0; i < 4; i++) parts.p[i] = partd + (size_t)i * NN * HID;

    // Pack weights + node into (hi,lo) bf16x2 operand format
    PackArgs pa;
    pa.w[0] = Wq; pa.w[1] = Wk; pa.w[2] = Wv; pa.w[3] = Wo; pa.w[4] = Wf1; pa.w[5] = Wf2;
    for (int i = 0; i < 4; i++) pa.pw[i] = pW4 + (size_t)i * (128*256);
    pa.pw[4] = pWf1; pa.pw[5] = pWf2;
    pa.node = node; pa.pnode = pNode;
    pack_all_kernel<<<768, 256>>>(pa);

    // Fused QKV projections
    QKVArgs qa;
    qa.W = pW4;
    qa.b[0] = bq; qa.b[1] = bk; qa.b[2] = bv;
    qa.O[0] = Qd; qa.O[1] = Kd; qa.O[2] = Vd;
    qkv_gemm_kernel<<<dim3(12, NN/GBM), 128, GEMM_SMEM>>>(pNode, qa);

    // Fused sparse attention + edge bias (packed output for Wo)
    attn_fused_kernel<<<NN, 256>>>(Qd, Kd, Vd, nbr, ef, We, be, pAttn);

    // Output projection (split-K 2) + fused reduce+bias+residual+LN1
    gemm_split_kernel<<<dim3(HID/GBN, NN/GBM, 2), 128, GEMM_SMEM>>>(pAttn, pW4 + 3*(128*256), parts, HID, 128, 64);
    add_ln_multi<2, true><<<NN, HID>>>(parts, bo, node, ln1g, ln1b, x1d, pX1);

    // FFN1 (packed output for FFN2)
    gemm_ffn1_kernel<<<dim3(FFN/GBN, NN/GBM), 128, GEMM_SMEM>>>(pX1, pWf1, bf1, pF, FFN, 128, 512);

    // FFN2 (split-K 4) + fused reduce+bias+residual+LN2
    gemm_split_kernel<<<dim3(HID/GBN, NN/GBM, 4), 128, GEMM_SMEM>>>(pF, pWf2, parts, HID, 512, 128);
    add_ln_multi<4, false><<<NN, HID>>>(parts, bf2, x1d, ln2g, ln2b, out, nullptr);
}